// round 4
// baseline (speedup 1.0000x reference)
#include <cuda_runtime.h>
#include <math.h>

#define D 50
#define E 300
#define KNB 63
#define NMAX 20000
#define BROW 80   // padded B row: 4 og-groups * 20 floats (16 data + 4 pad)

// ---- device scratch ----
__device__ float g_ent[NMAX * D];
__device__ float g_node[NMAX * D];
__device__ __align__(16) float g_Wt2[D * D * BROW];   // [(i*50+j)][80]
__device__ __align__(16) float g_WpT2[E * BROW];      // [k][80]

// ---- f32x2 helpers ----
__device__ __forceinline__ void fma2(unsigned long long& acc,
                                     unsigned long long a,
                                     unsigned long long b) {
    asm("fma.rn.f32x2 %0, %1, %2, %0;" : "+l"(acc) : "l"(a), "l"(b));
}
__device__ __forceinline__ unsigned long long dup2(float x) {
    unsigned long long r;
    asm("mov.b64 %0, {%1, %1};" : "=l"(r) : "f"(x));
    return r;
}
__device__ __forceinline__ float2 unpack2(unsigned long long v) {
    float2 r;
    asm("mov.b64 {%0, %1}, %2;" : "=f"(r.x), "=f"(r.y) : "l"(v));
    return r;
}
// ---- cp.async helpers ----
__device__ __forceinline__ void cp16(void* smem_dst, const void* gmem_src) {
    unsigned s = (unsigned)__cvta_generic_to_shared(smem_dst);
    asm volatile("cp.async.cg.shared.global [%0], [%1], 16;" :: "r"(s), "l"(gmem_src));
}
#define CP_COMMIT() asm volatile("cp.async.commit_group;" ::: "memory")
#define CP_WAIT0()  asm volatile("cp.async.wait_group 0;" ::: "memory")

// ============================================================
// Prep: pad/transpose weights into [row][80] og-grouped layout
// ============================================================
__global__ void prep_kernel(const float* __restrict__ Wp,
                            const float* __restrict__ Wbil) {
    int idx = blockIdx.x * blockDim.x + threadIdx.x;
    if (idx < D * D * BROW) {
        int r = idx / BROW, col = idx % BROW;
        int og = col / 20, cc = col % 20;
        int o = og * 16 + cc;
        int i = r / D, j = r % D;
        g_Wt2[idx] = (cc < 16 && o < D) ? Wbil[o * (D * D) + i * D + j] : 0.f;
    }
    if (idx < E * BROW) {
        int k = idx / BROW, col = idx % BROW;
        int og = col / 20, cc = col % 20;
        int o = og * 16 + cc;
        g_WpT2[idx] = (cc < 16 && o < D) ? Wp[o * E + k] : 0.f;
    }
}

// ============================================================
// Kernel A: ent = entity @ Wp^T + bp (f32x2 packed, unchanged from R3)
// ============================================================
__global__ __launch_bounds__(128) void ent_proj_kernel(
    const float* __restrict__ entity, const float* __restrict__ bp, int N) {
    __shared__ float As[50 * 66];
    __shared__ float Bs[50 * BROW];
    int tid = threadIdx.x;
    int ng = tid >> 2, og = tid & 3;
    int n0 = blockIdx.x * 64;

    unsigned long long acc[2][8];
    #pragma unroll
    for (int s = 0; s < 2; s++)
        #pragma unroll
        for (int p = 0; p < 8; p++) acc[s][p] = 0ull;

    for (int c0 = 0; c0 < E; c0 += 50) {
        __syncthreads();
        for (int idx = tid; idx < 64 * 50; idx += 128) {
            int n = idx / 50, k = idx % 50;
            int gn = n0 + n;
            As[k * 66 + n] = (gn < N) ? entity[(size_t)gn * E + c0 + k] : 0.f;
        }
        for (int idx = tid; idx < 50 * BROW; idx += 128)
            Bs[idx] = g_WpT2[(size_t)c0 * BROW + idx];
        __syncthreads();
        #pragma unroll 10
        for (int k = 0; k < 50; k++) {
            float2 ap = *(const float2*)&As[k * 66 + 2 * ng];
            unsigned long long aA = dup2(ap.x), aB = dup2(ap.y);
            const ulonglong2* bpp = (const ulonglong2*)&Bs[k * BROW + og * 20];
            ulonglong2 u0 = bpp[0], u1 = bpp[1], u2 = bpp[2], u3 = bpp[3];
            fma2(acc[0][0], aA, u0.x); fma2(acc[0][1], aA, u0.y);
            fma2(acc[0][2], aA, u1.x); fma2(acc[0][3], aA, u1.y);
            fma2(acc[0][4], aA, u2.x); fma2(acc[0][5], aA, u2.y);
            fma2(acc[0][6], aA, u3.x); fma2(acc[0][7], aA, u3.y);
            fma2(acc[1][0], aB, u0.x); fma2(acc[1][1], aB, u0.y);
            fma2(acc[1][2], aB, u1.x); fma2(acc[1][3], aB, u1.y);
            fma2(acc[1][4], aB, u2.x); fma2(acc[1][5], aB, u2.y);
            fma2(acc[1][6], aB, u3.x); fma2(acc[1][7], aB, u3.y);
        }
    }
    #pragma unroll
    for (int s = 0; s < 2; s++) {
        int n = n0 + 2 * ng + s;
        if (n >= N) continue;
        #pragma unroll
        for (int p = 0; p < 8; p++) {
            int o = og * 16 + 2 * p;
            float2 v = unpack2(acc[s][p]);
            if (o < D)     g_ent[(size_t)n * D + o]     = v.x + bp[o];
            if (o + 1 < D) g_ent[(size_t)n * D + o + 1] = v.y + bp[o + 1];
        }
    }
}

// ============================================================
// Kernel B: bilinear, 256 threads / 64 nodes, thread = 1 node x 16 outs.
// cp.async double-buffered weight slab (16KB per i), 1 barrier per i.
// Dynamic smem: qs 12.8K + es 12.8K + Bs 32K = 57.6KB
// ============================================================
__global__ __launch_bounds__(256) void bilinear_kernel(
    const float* __restrict__ query, const float* __restrict__ bbil, int N) {
    extern __shared__ float sm[];
    float* qs = sm;                 // [50][64]
    float* es = sm + 50 * 64;       // [50][64]
    float* Bs = sm + 2 * 50 * 64;   // [2][50*80]
    int tid = threadIdx.x;
    int ng = tid >> 2, og = tid & 3;     // node 0..63, out-group 0..3
    int n0 = blockIdx.x * 64;

    // prefetch slab i=0
    {
        const float* src = g_Wt2;
        float* dst = Bs;
        for (int c = tid; c < 1000; c += 256)
            cp16(dst + c * 4, src + c * 4);
        CP_COMMIT();
    }
    // load q/e tiles (transposed [x][node])
    for (int idx = tid; idx < 64 * 50; idx += 256) {
        int n = idx / 50, x = idx % 50;
        int gn = n0 + n;
        float qv = 0.f, ev = 0.f;
        if (gn < N) {
            qv = query[(size_t)gn * D + x];
            ev = g_ent[(size_t)gn * D + x];
        }
        qs[x * 64 + n] = qv;
        es[x * 64 + n] = ev;
    }

    unsigned long long acc[8];
    #pragma unroll
    for (int p = 0; p < 8; p++) acc[p] = 0ull;

    for (int i = 0; i < D; i++) {
        CP_WAIT0();
        __syncthreads();
        if (i + 1 < D) {
            const float* src = g_Wt2 + (size_t)((i + 1) * D) * BROW;
            float* dst = &Bs[((i + 1) & 1) * 4000];
            for (int c = tid; c < 1000; c += 256)
                cp16(dst + c * 4, src + c * 4);
            CP_COMMIT();
        }
        float qv = qs[i * 64 + ng];
        const float* Bb = &Bs[(i & 1) * 4000];
        #pragma unroll 10
        for (int j = 0; j < 50; j++) {
            float ev = es[j * 64 + ng];
            unsigned long long aa = dup2(qv * ev);
            const ulonglong2* bpp = (const ulonglong2*)&Bb[j * BROW + og * 20];
            ulonglong2 u0 = bpp[0], u1 = bpp[1], u2 = bpp[2], u3 = bpp[3];
            fma2(acc[0], aa, u0.x); fma2(acc[1], aa, u0.y);
            fma2(acc[2], aa, u1.x); fma2(acc[3], aa, u1.y);
            fma2(acc[4], aa, u2.x); fma2(acc[5], aa, u2.y);
            fma2(acc[6], aa, u3.x); fma2(acc[7], aa, u3.y);
        }
    }

    int n = n0 + ng;
    if (n < N) {
        #pragma unroll
        for (int p = 0; p < 8; p++) {
            int o = og * 16 + 2 * p;
            float2 v = unpack2(acc[p]);
            if (o < D)     g_node[(size_t)n * D + o]     = v.x + bbil[o];
            if (o + 1 < D) g_node[(size_t)n * D + o + 1] = v.y + bbil[o + 1];
        }
    }
}

// ============================================================
// Kernel C: fused tail. 512 threads / 10 nodes, 50 threads per node.
// Phase 1: k-interleaved 2-way split per d-pair (2x MLP), __ldcs streams.
// Phase 2: thread r computes output o=r directly.
// ============================================================
#define TNODES 10
__global__ __launch_bounds__(512) void tail_kernel(
    const float* __restrict__ nbr, const float* __restrict__ scores,
    const float* __restrict__ Wg, const float* __restrict__ g_bias,
    const float* __restrict__ Wr, const float* __restrict__ br,
    float* __restrict__ out, int N) {
    __shared__ float Wgs[50 * 51];
    __shared__ float Wrs[50];
    __shared__ float gbs[50];
    __shared__ float sP[2][TNODES][50];
    __shared__ float sc_sm[TNODES][64];
    __shared__ float part[TNODES][50];
    int tid = threadIdx.x;
    int nb = blockIdx.x * TNODES;

    for (int idx = tid; idx < 2500; idx += 512)
        Wgs[(idx / 50) * 51 + idx % 50] = Wg[idx];
    if (tid < 50) { Wrs[tid] = Wr[tid]; gbs[tid] = g_bias[tid]; }
    for (int idx = tid; idx < TNODES * 64; idx += 512) {
        int ln = idx >> 6, c = idx & 63;
        int n = nb + ln;
        sc_sm[ln][c] = (n < N) ? scores[(size_t)n * (KNB + 1) + c] : 0.f;
    }
    __syncthreads();

    int tn = tid / 50, r = tid % 50;
    bool act = (tid < 500) && (nb + tn < N);

    if (act) {
        int n = nb + tn;
        int tc = r % 25, kh = r / 25;            // d-pair, k-parity
        const float* base = nbr + (size_t)n * (KNB * D) + 2 * tc;
        float a0 = 0.f, a1 = 0.f;
        // uniform main loop: k = kh, kh+2, ..., < 62  (31 iters each)
        #pragma unroll 8
        for (int k = kh; k < 62; k += 2) {
            float w = sc_sm[tn][k];
            float2 u = __ldcs((const float2*)(base + (size_t)k * D));
            a0 += w * u.x; a1 += w * u.y;
        }
        if (kh == 0) {              // k = 62
            float w = sc_sm[tn][62];
            float2 u = __ldcs((const float2*)(base + (size_t)62 * D));
            a0 += w * u.x; a1 += w * u.y;
        } else {                    // node's own embedding term
            float w = sc_sm[tn][KNB];
            float2 v = *(const float2*)&g_node[(size_t)n * D + 2 * tc];
            a0 += w * v.x; a1 += w * v.y;
        }
        sP[kh][tn][2 * tc]     = a0;
        sP[kh][tn][2 * tc + 1] = a1;
    }
    __syncthreads();

    if (act) {
        int o = r;
        float a = gbs[o];
        #pragma unroll 10
        for (int d = 0; d < 50; d++)
            a += (sP[0][tn][d] + sP[1][tn][d]) * Wgs[o * 51 + d];
        float f = (a > 0.f) ? a : expm1f(a);
        part[tn][o] = f * Wrs[o];
    }
    __syncthreads();

    if (tid < TNODES && nb + tid < N) {
        float rr = 0.f;
        #pragma unroll
        for (int c = 0; c < 50; c++) rr += part[tid][c];
        out[nb + tid] = rr + br[0];
    }
}

// ============================================================
extern "C" void kernel_launch(void* const* d_in, const int* in_sizes, int n_in,
                              void* d_out, int out_size) {
    const float* query  = (const float*)d_in[0];
    const float* entity = (const float*)d_in[1];
    const float* nbr    = (const float*)d_in[2];
    const float* scores = (const float*)d_in[3];
    const float* Wp     = (const float*)d_in[4];
    const float* bp     = (const float*)d_in[5];
    const float* Wbil   = (const float*)d_in[6];
    const float* bbil   = (const float*)d_in[7];
    const float* Wg     = (const float*)d_in[8];
    const float* gbias  = (const float*)d_in[9];
    const float* Wr     = (const float*)d_in[10];
    const float* br     = (const float*)d_in[11];
    float* out = (float*)d_out;

    int N = in_sizes[0] / D;
    if (N > NMAX) N = NMAX;

    static bool attr_set = false;
    if (!attr_set) {
        cudaFuncSetAttribute(bilinear_kernel,
                             cudaFuncAttributeMaxDynamicSharedMemorySize, 57600);
        attr_set = true;
    }

    prep_kernel<<<(D * D * BROW + 255) / 256, 256>>>(Wp, Wbil);
    ent_proj_kernel<<<(N + 63) / 64, 128>>>(entity, bp, N);
    bilinear_kernel<<<(N + 63) / 64, 256, 57600>>>(query, bbil, N);
    tail_kernel<<<(N + TNODES - 1) / TNODES, 512>>>(nbr, scores, Wg, gbias, Wr, br, out, N);
}

// round 6
// speedup vs baseline: 2.4633x; 2.4633x over previous
#include <cuda_runtime.h>
#include <math.h>

#define D 50
#define E 300
#define KNB 63
#define NMAX 20000
#define BROW 80   // padded B row: 4 og-groups * 20 floats (16 data + 4 pad)

// ---- device scratch (16B-aligned: accessed via vector loads) ----
__device__ __align__(16) float g_ent[NMAX * D];
__device__ __align__(16) float g_nodeA[NMAX * D];    // bilinear partial: i in [0,25)
__device__ __align__(16) float g_nodeB[NMAX * D];    // bilinear partial: i in [25,50)
__device__ __align__(16) float g_Wt2[D * D * BROW];
__device__ __align__(16) float g_WpT2[E * BROW];

// ---- f32x2 helpers ----
__device__ __forceinline__ void fma2(unsigned long long& acc,
                                     unsigned long long a,
                                     unsigned long long b) {
    asm("fma.rn.f32x2 %0, %1, %2, %0;" : "+l"(acc) : "l"(a), "l"(b));
}
__device__ __forceinline__ unsigned long long dup2(float x) {
    unsigned long long r;
    asm("mov.b64 %0, {%1, %1};" : "=l"(r) : "f"(x));
    return r;
}
__device__ __forceinline__ float2 unpack2(unsigned long long v) {
    float2 r;
    asm("mov.b64 {%0, %1}, %2;" : "=f"(r.x), "=f"(r.y) : "l"(v));
    return r;
}

// ============================================================
// Prep: pad/transpose weights into [row][80] og-grouped layout
// ============================================================
__global__ void prep_kernel(const float* __restrict__ Wp,
                            const float* __restrict__ Wbil) {
    int idx = blockIdx.x * blockDim.x + threadIdx.x;
    if (idx < D * D * BROW) {
        int r = idx / BROW, col = idx % BROW;
        int og = col / 20, cc = col % 20;
        int o = og * 16 + cc;
        int i = r / D, j = r % D;
        g_Wt2[idx] = (cc < 16 && o < D) ? Wbil[o * (D * D) + i * D + j] : 0.f;
    }
    if (idx < E * BROW) {
        int k = idx / BROW, col = idx % BROW;
        int og = col / 20, cc = col % 20;
        int o = og * 16 + cc;
        g_WpT2[idx] = (cc < 16 && o < D) ? Wp[o * E + k] : 0.f;
    }
}

// ============================================================
// Kernel A: ent = entity @ Wp^T + bp (f32x2 packed, R3-proven)
// ============================================================
__global__ __launch_bounds__(128) void ent_proj_kernel(
    const float* __restrict__ entity, const float* __restrict__ bp, int N) {
    __shared__ __align__(16) float As[50 * 66];
    __shared__ __align__(16) float Bs[50 * BROW];
    int tid = threadIdx.x;
    int ng = tid >> 2, og = tid & 3;
    int n0 = blockIdx.x * 64;

    unsigned long long acc[2][8];
    #pragma unroll
    for (int s = 0; s < 2; s++)
        #pragma unroll
        for (int p = 0; p < 8; p++) acc[s][p] = 0ull;

    for (int c0 = 0; c0 < E; c0 += 50) {
        __syncthreads();
        for (int idx = tid; idx < 64 * 50; idx += 128) {
            int n = idx / 50, k = idx % 50;
            int gn = n0 + n;
            As[k * 66 + n] = (gn < N) ? entity[(size_t)gn * E + c0 + k] : 0.f;
        }
        for (int idx = tid; idx < 50 * BROW; idx += 128)
            Bs[idx] = g_WpT2[(size_t)c0 * BROW + idx];
        __syncthreads();
        #pragma unroll 10
        for (int k = 0; k < 50; k++) {
            float2 ap = *(const float2*)&As[k * 66 + 2 * ng];
            unsigned long long aA = dup2(ap.x), aB = dup2(ap.y);
            const ulonglong2* bpp = (const ulonglong2*)&Bs[k * BROW + og * 20];
            ulonglong2 u0 = bpp[0], u1 = bpp[1], u2 = bpp[2], u3 = bpp[3];
            fma2(acc[0][0], aA, u0.x); fma2(acc[0][1], aA, u0.y);
            fma2(acc[0][2], aA, u1.x); fma2(acc[0][3], aA, u1.y);
            fma2(acc[0][4], aA, u2.x); fma2(acc[0][5], aA, u2.y);
            fma2(acc[0][6], aA, u3.x); fma2(acc[0][7], aA, u3.y);
            fma2(acc[1][0], aB, u0.x); fma2(acc[1][1], aB, u0.y);
            fma2(acc[1][2], aB, u1.x); fma2(acc[1][3], aB, u1.y);
            fma2(acc[1][4], aB, u2.x); fma2(acc[1][5], aB, u2.y);
            fma2(acc[1][6], aB, u3.x); fma2(acc[1][7], aB, u3.y);
        }
    }
    #pragma unroll
    for (int s = 0; s < 2; s++) {
        int n = n0 + 2 * ng + s;
        if (n >= N) continue;
        #pragma unroll
        for (int p = 0; p < 8; p++) {
            int o = og * 16 + 2 * p;
            float2 v = unpack2(acc[s][p]);
            if (o < D)     g_ent[(size_t)n * D + o]     = v.x + bp[o];
            if (o + 1 < D) g_ent[(size_t)n * D + o + 1] = v.y + bp[o + 1];
        }
    }
}

// ============================================================
// Kernel B: bilinear, R3 inner loop; i-range split across gridDim.y=2
// (blockIdx.y: i in [0,25) -> g_nodeA, [25,50) -> g_nodeB).
// block: 64 nodes, 128 threads; thread: 2 nodes x 16 outputs.
// ============================================================
__global__ __launch_bounds__(128) void bilinear_kernel(
    const float* __restrict__ query, int N) {
    __shared__ __align__(16) float qs[26 * 66];
    __shared__ __align__(16) float es[50 * 66];
    __shared__ __align__(16) float Bs[50 * BROW];
    int tid = threadIdx.x;
    int ng = tid >> 2, og = tid & 3;
    int n0 = blockIdx.x * 64;
    int i0 = blockIdx.y * 25;
    float* outbuf = blockIdx.y ? g_nodeB : g_nodeA;

    for (int idx = tid; idx < 64 * 50; idx += 128) {
        int n = idx / 50, x = idx % 50;
        int gn = n0 + n;
        es[x * 66 + n] = (gn < N) ? g_ent[(size_t)gn * D + x] : 0.f;
    }
    for (int idx = tid; idx < 64 * 25; idx += 128) {
        int n = idx / 25, x = idx % 25;
        int gn = n0 + n;
        qs[x * 66 + n] = (gn < N) ? query[(size_t)gn * D + i0 + x] : 0.f;
    }

    unsigned long long acc[2][8];
    #pragma unroll
    for (int s = 0; s < 2; s++)
        #pragma unroll
        for (int p = 0; p < 8; p++) acc[s][p] = 0ull;

    for (int ii = 0; ii < 25; ii++) {
        __syncthreads();
        const float* src = g_Wt2 + (size_t)((i0 + ii) * D) * BROW;
        for (int idx = tid; idx < 50 * BROW; idx += 128)
            Bs[idx] = src[idx];
        __syncthreads();
        float2 qp = *(const float2*)&qs[ii * 66 + 2 * ng];
        #pragma unroll 10
        for (int j = 0; j < 50; j++) {
            float2 ep = *(const float2*)&es[j * 66 + 2 * ng];
            unsigned long long aA = dup2(qp.x * ep.x);
            unsigned long long aB = dup2(qp.y * ep.y);
            const ulonglong2* bpp = (const ulonglong2*)&Bs[j * BROW + og * 20];
            ulonglong2 u0 = bpp[0], u1 = bpp[1], u2 = bpp[2], u3 = bpp[3];
            fma2(acc[0][0], aA, u0.x); fma2(acc[0][1], aA, u0.y);
            fma2(acc[0][2], aA, u1.x); fma2(acc[0][3], aA, u1.y);
            fma2(acc[0][4], aA, u2.x); fma2(acc[0][5], aA, u2.y);
            fma2(acc[0][6], aA, u3.x); fma2(acc[0][7], aA, u3.y);
            fma2(acc[1][0], aB, u0.x); fma2(acc[1][1], aB, u0.y);
            fma2(acc[1][2], aB, u1.x); fma2(acc[1][3], aB, u1.y);
            fma2(acc[1][4], aB, u2.x); fma2(acc[1][5], aB, u2.y);
            fma2(acc[1][6], aB, u3.x); fma2(acc[1][7], aB, u3.y);
        }
    }

    #pragma unroll
    for (int s = 0; s < 2; s++) {
        int n = n0 + 2 * ng + s;
        if (n >= N) continue;
        #pragma unroll
        for (int p = 0; p < 8; p++) {
            int o = og * 16 + 2 * p;
            float2 v = unpack2(acc[s][p]);
            if (o < D)     outbuf[(size_t)n * D + o]     = v.x;
            if (o + 1 < D) outbuf[(size_t)n * D + o + 1] = v.y;
        }
    }
}

// ============================================================
// Kernel C: fused tail (node = A + B + bbil folded in; full k-unroll)
// block: 8 nodes, 256 threads, 1 warp/node, lanes 0..24 active in phase 1
// ============================================================
__global__ __launch_bounds__(256) void tail_kernel(
    const float* __restrict__ nbr, const float* __restrict__ scores,
    const float* __restrict__ bbil,
    const float* __restrict__ Wg, const float* __restrict__ g_bias,
    const float* __restrict__ Wr, const float* __restrict__ br,
    float* __restrict__ out, int N) {
    __shared__ __align__(16) float Wgs[50 * 51];
    __shared__ __align__(16) float s_sm[8][50];
    __shared__ __align__(16) float Wrs[50];
    __shared__ __align__(16) float gbs[50];
    __shared__ __align__(16) float bbs[52];
    int tid = threadIdx.x;

    for (int idx = tid; idx < 2500; idx += 256) {
        int o = idx / 50, d = idx % 50;
        Wgs[o * 51 + d] = Wg[idx];
    }
    if (tid < 50) { Wrs[tid] = Wr[tid]; gbs[tid] = g_bias[tid]; bbs[tid] = bbil[tid]; }
    __syncthreads();

    int warp = tid >> 5, lane = tid & 31;
    int n = blockIdx.x * 8 + warp;
    if (n >= N) return;

    const float* base = nbr + (size_t)n * KNB * D;
    const float* sc   = scores + (size_t)n * (KNB + 1);

    if (lane < 25) {
        float wK = sc[KNB];
        float2 vA = *(const float2*)&g_nodeA[(size_t)n * D + 2 * lane];
        float2 vB = *(const float2*)&g_nodeB[(size_t)n * D + 2 * lane];
        float bbx = bbs[2 * lane], bby = bbs[2 * lane + 1];
        float sx = wK * (vA.x + vB.x + bbx);
        float sy = wK * (vA.y + vB.y + bby);
        float tx_ = 0.f, ty_ = 0.f;
        #pragma unroll
        for (int k = 0; k < 62; k += 2) {
            float w0 = sc[k], w1 = sc[k + 1];
            float2 u0 = *(const float2*)(base + (size_t)k * D + 2 * lane);
            float2 u1 = *(const float2*)(base + (size_t)(k + 1) * D + 2 * lane);
            sx += w0 * u0.x; sy += w0 * u0.y;
            tx_ += w1 * u1.x; ty_ += w1 * u1.y;
        }
        {
            float w = sc[62];
            float2 u = *(const float2*)(base + (size_t)62 * D + 2 * lane);
            sx += w * u.x; sy += w * u.y;
        }
        s_sm[warp][2 * lane]     = sx + tx_;
        s_sm[warp][2 * lane + 1] = sy + ty_;
    }
    __syncwarp();

    float r = 0.f;
    #pragma unroll
    for (int rep = 0; rep < 2; rep++) {
        int o = lane + 32 * rep;
        if (o < D) {
            float a = gbs[o];
            #pragma unroll 10
            for (int d = 0; d < D; d++)
                a += s_sm[warp][d] * Wgs[o * 51 + d];
            float f = (a > 0.f) ? a : expm1f(a);
            r += f * Wrs[o];
        }
    }
    #pragma unroll
    for (int off = 16; off; off >>= 1)
        r += __shfl_down_sync(0xffffffffu, r, off);
    if (lane == 0) out[n] = r + br[0];
}

// ============================================================
extern "C" void kernel_launch(void* const* d_in, const int* in_sizes, int n_in,
                              void* d_out, int out_size) {
    const float* query  = (const float*)d_in[0];
    const float* entity = (const float*)d_in[1];
    const float* nbr    = (const float*)d_in[2];
    const float* scores = (const float*)d_in[3];
    const float* Wp     = (const float*)d_in[4];
    const float* bp     = (const float*)d_in[5];
    const float* Wbil   = (const float*)d_in[6];
    const float* bbil   = (const float*)d_in[7];
    const float* Wg     = (const float*)d_in[8];
    const float* gbias  = (const float*)d_in[9];
    const float* Wr     = (const float*)d_in[10];
    const float* br     = (const float*)d_in[11];
    float* out = (float*)d_out;

    int N = in_sizes[0] / D;
    if (N > NMAX) N = NMAX;

    prep_kernel<<<(D * D * BROW + 255) / 256, 256>>>(Wp, Wbil);
    ent_proj_kernel<<<(N + 63) / 64, 128>>>(entity, bp, N);
    dim3 bgrid((N + 63) / 64, 2);
    bilinear_kernel<<<bgrid, 128>>>(query, N);
    tail_kernel<<<(N + 7) / 8, 256>>>(nbr, scores, bbil, Wg, gbias, Wr, br, out, N);
}